// round 14
// baseline (speedup 1.0000x reference)
#include <cuda_runtime.h>

// KANLayer_60464549593380 on GB300 (sm_103a):
//   out[b] = sum_d P_d(tanh(x[b,d])), P_d = degree-8 monomial poly from
//   w = hweights @ coeffs (summation reorder + Chebyshev->monomial fold).
// R14 = R13 + row-pair ILP (2 independent chains/iter, MLP 4), Estrin
// evaluation (chain 36->20 cyc), paired float2 STS. 8192 warps, coalesced
// LDG.64, shuffle-free loop.

#define DEG   8
#define NF    9
#define DDIM  256
#define FDIM  2304
#define F4DIM 576
#define ROWS  32            // rows per block
#define NPAIR (ROWS / 2)    // 16 row pairs
#define PP2   129           // part2[] pitch in float2

__device__ float g_w[FDIM];

typedef unsigned long long u64;

// ---------------- packed f32x2 / MUFU helpers ----------------
__device__ __forceinline__ u64 fma2(u64 a, u64 b, u64 c) {
    u64 d; asm("fma.rn.f32x2 %0, %1, %2, %3;" : "=l"(d) : "l"(a), "l"(b), "l"(c));
    return d;
}
__device__ __forceinline__ u64 add2(u64 a, u64 b) {
    u64 d; asm("add.rn.f32x2 %0, %1, %2;" : "=l"(d) : "l"(a), "l"(b));
    return d;
}
__device__ __forceinline__ u64 mul2(u64 a, u64 b) {
    u64 d; asm("mul.rn.f32x2 %0, %1, %2;" : "=l"(d) : "l"(a), "l"(b));
    return d;
}
__device__ __forceinline__ u64 pack2(float lo, float hi) {
    u64 d; asm("mov.b64 %0, {%1, %2};" : "=l"(d) : "f"(lo), "f"(hi));
    return d;
}
__device__ __forceinline__ float unpack_sum(u64 v) {
    float lo, hi;
    asm("mov.b64 {%0, %1}, %2;" : "=f"(lo), "=f"(hi) : "l"(v));
    return lo + hi;
}
__device__ __forceinline__ float ex2a(float v) {
    float r; asm("ex2.approx.ftz.f32 %0, %1;" : "=f"(r) : "f"(v)); return r;
}
__device__ __forceinline__ float rcpa(float v) {
    float r; asm("rcp.approx.ftz.f32 %0, %1;" : "=f"(r) : "f"(v)); return r;
}

// Packed tanh of 2 values: t = (1-e)/(1+e), e = exp(-2v).
__device__ __forceinline__ u64 tanh2(u64 v2) {
    const u64 ONE2  = 0x3f8000003f800000ull;   // (1.0f, 1.0f)
    const u64 NEG12 = 0xbf800000bf800000ull;   // (-1.0f, -1.0f)
    const u64 SC2   = 0xc038aa3bc038aa3bull;   // (-2*log2e) x2
    u64 s2 = mul2(v2, SC2);
    float slo, shi;
    asm("mov.b64 {%0, %1}, %2;" : "=f"(slo), "=f"(shi) : "l"(s2));
    u64 e2 = pack2(ex2a(slo), ex2a(shi));
    u64 num = fma2(e2, NEG12, ONE2);           // 1 - e
    u64 den = add2(e2, ONE2);                  // 1 + e
    float dlo, dhi;
    asm("mov.b64 {%0, %1}, %2;" : "=f"(dlo), "=f"(dhi) : "l"(den));
    u64 r2 = pack2(rcpa(dlo), rcpa(dhi));
    return mul2(num, r2);
}

// Degree-8 packed Estrin: P(t) = (c0+c1 t) + (c2+c3 t) t2
//   + [(c4+c5 t) + (c6+c7 t) t2] t4 + c8 t8.  Chain ~20 cyc vs Horner 36.
__device__ __forceinline__ u64 estrin8(const u64* __restrict__ c, u64 tp) {
    u64 t2 = mul2(tp, tp);
    u64 t4 = mul2(t2, t2);
    u64 t8 = mul2(t4, t4);
    u64 p01 = fma2(c[1], tp, c[0]);
    u64 p23 = fma2(c[3], tp, c[2]);
    u64 p45 = fma2(c[5], tp, c[4]);
    u64 p67 = fma2(c[7], tp, c[6]);
    u64 q0  = fma2(p23, t2, p01);
    u64 q1  = fma2(p67, t2, p45);
    u64 r   = fma2(q1, t4, q0);
    return fma2(c[8], t8, r);
}

// ---------------- Prep: w[f] = sum_n hw[n]*coeffs[n,f] ----------------
__global__ void k_wprep(const float4* __restrict__ c4,
                        const float* __restrict__ hw, int N) {
    __shared__ float4 red[128];
    const int col = blockIdx.x;
    const int t   = threadIdx.x;
    float4 s = make_float4(0.f, 0.f, 0.f, 0.f);
    for (int n = t; n < N; n += 128) {
        float  h = hw[n];
        float4 v = c4[(size_t)n * F4DIM + col];
        s.x = fmaf(h, v.x, s.x);
        s.y = fmaf(h, v.y, s.y);
        s.z = fmaf(h, v.z, s.z);
        s.w = fmaf(h, v.w, s.w);
    }
    red[t] = s;
    __syncthreads();
    #pragma unroll
    for (int o = 64; o >= 1; o >>= 1) {
        if (t < o) {
            float4 b = red[t + o];
            red[t].x += b.x; red[t].y += b.y; red[t].z += b.z; red[t].w += b.w;
        }
        __syncthreads();
    }
    if (t == 0) ((float4*)g_w)[col] = red[0];
}

// Chebyshev -> monomial for one dim's 9 weights.
__device__ __forceinline__ void cheb2mono(const float* __restrict__ w, float* a) {
    a[0] = w[0] - w[2] + w[4] - w[6] + w[8];
    a[1] = w[1] - 3.f * w[3] + 5.f * w[5] - 7.f * w[7];
    a[2] = 2.f * w[2] - 8.f * w[4] + 18.f * w[6] - 32.f * w[8];
    a[3] = 4.f * w[3] - 20.f * w[5] + 56.f * w[7];
    a[4] = 8.f * w[4] - 48.f * w[6] + 160.f * w[8];
    a[5] = 16.f * w[5] - 112.f * w[7];
    a[6] = 32.f * w[6] - 256.f * w[8];
    a[7] = 64.f * w[7];
    a[8] = 128.f * w[8];
}

// ---------------- Main ----------------
// 256 threads = 8 warps, 32 rows/block, grid 1024 (8192 warps).
// Warp w: quarter q = w&3 (dims 64q..64q+63), row group g = w>>2
// (rows 16g..16g+15, as 8 pairs). Lane owns 2 fixed dims: d0 = 64q+2*lane.
// Iter i: rows (16g+2i, 16g+2i+1) -- two independent LDG/tanh/Estrin chains,
// one combined float2 STS. No shuffles, no loop barriers.
__global__ void __launch_bounds__(256)
k_main(const float* __restrict__ x, float* __restrict__ out, int B) {
    __shared__ float2 part2[NPAIR][PP2];          // 16.5 KB
    __shared__ float2 red2[NPAIR][16];            // 2 KB
    const int t    = threadIdx.x;
    const int lane = t & 31;
    const int w    = t >> 5;
    const int q    = w & 3;
    const int g    = w >> 2;
    const size_t row0 = (size_t)blockIdx.x * ROWS;

    // Coefficients for this lane's 2 dims, packed as one chain.
    u64 c[NF];
    {
        const int d0 = 64 * q + 2 * lane;
        const float2* wp = (const float2*)(g_w + d0 * NF);  // 18 floats, 8B-aligned
        float wb[2 * NF];
        #pragma unroll
        for (int k = 0; k < NF; ++k) ((float2*)wb)[k] = wp[k];
        float alo[NF], ahi[NF];
        cheb2mono(wb, alo);
        cheb2mono(wb + NF, ahi);
        #pragma unroll
        for (int j = 0; j < NF; ++j) c[j] = pack2(alo[j], ahi[j]);
    }

    // float2 index of row r's slice: (row0 + r)*128 + 32q + lane.
    const float2* xp = (const float2*)x + (row0 + 16 * g) * 128 + 32 * q + lane;

    float2 xa = xp[0];
    float2 xb = xp[128];
    #pragma unroll
    for (int i = 0; i < 8; ++i) {
        float2 na, nb;
        if (i < 7) {
            na = xp[(2 * i + 2) * 128];
            nb = xp[(2 * i + 3) * 128];
        }

        u64 ta = tanh2(pack2(xa.x, xa.y));       // two independent chains
        u64 tb = tanh2(pack2(xb.x, xb.y));
        u64 ha = estrin8(c, ta);
        u64 hb = estrin8(c, tb);
        part2[8 * g + i][32 * q + lane] =
            make_float2(unpack_sum(ha), unpack_sum(hb));

        xa = na; xb = nb;
    }

    __syncthreads();
    // Tail step 1: 256 threads; thread (pair, seg) sums 8 of 128 float2s.
    {
        const int pr = t >> 4, seg = t & 15;
        const float2* pp = part2[pr] + 8 * seg;
        float sx = 0.f, sy = 0.f;
        #pragma unroll
        for (int k = 0; k < 8; ++k) { sx += pp[k].x; sy += pp[k].y; }
        red2[pr][seg] = make_float2(sx, sy);
    }
    __syncthreads();
    // Tail step 2: 16 threads; each sums its pair's 16 sub-partials.
    if (t < NPAIR) {
        const float2* rr = red2[t];
        float sx = 0.f, sy = 0.f;
        #pragma unroll
        for (int k = 0; k < 16; ++k) { sx += rr[k].x; sy += rr[k].y; }
        size_t row = row0 + 2 * t;
        if (row + 1 < (size_t)B + 1) {            // B multiple of 32; always true
            out[row]     = sx;
            out[row + 1] = sy;
        }
    }
}

extern "C" void kernel_launch(void* const* d_in, const int* in_sizes, int n_in,
                              void* d_out, int out_size) {
    const float* x      = (const float*)d_in[0];
    const float* coeffs = (const float*)d_in[1];
    const float* hw     = (const float*)d_in[2];
    float* out = (float*)d_out;

    const int B = out_size;       // 32768 = 1024 * 32
    const int N = in_sizes[2];    // 256

    k_wprep<<<F4DIM, 128>>>((const float4*)coeffs, hw, N);
    k_main<<<(B + ROWS - 1) / ROWS, 256>>>(x, out, B);
}

// round 15
// speedup vs baseline: 1.1550x; 1.1550x over previous
#include <cuda_runtime.h>

// KANLayer_60464549593380 on GB300 (sm_103a):
//   out[b] = sum_d P_d(tanh(x[b,d])), P_d = degree-8 monomial poly from
//   w = hweights @ coeffs (summation reorder + Chebyshev->monomial fold).
// R15 = R13 (best: 15.1us) + 4-deep rolling register prefetch.
// Rationale: dur == 33.5MB / achieved-BW in ALL rounds; depth-1 prefetch
// caps in-flight bytes at 8KB/SM -> ~2.5TB/s by Little's law. Depth 4
// quadruples outstanding bytes; everything else byte-identical to R13.

#define DEG   8
#define NF    9
#define DDIM  256
#define FDIM  2304
#define F4DIM 576
#define ROWS  32            // rows per block
#define PPITCH 129          // part[] pitch in floats
#define PF    4             // prefetch depth

__device__ float g_w[FDIM];

typedef unsigned long long u64;

// ---------------- packed f32x2 / MUFU helpers ----------------
__device__ __forceinline__ u64 fma2(u64 a, u64 b, u64 c) {
    u64 d; asm("fma.rn.f32x2 %0, %1, %2, %3;" : "=l"(d) : "l"(a), "l"(b), "l"(c));
    return d;
}
__device__ __forceinline__ u64 add2(u64 a, u64 b) {
    u64 d; asm("add.rn.f32x2 %0, %1, %2;" : "=l"(d) : "l"(a), "l"(b));
    return d;
}
__device__ __forceinline__ u64 mul2(u64 a, u64 b) {
    u64 d; asm("mul.rn.f32x2 %0, %1, %2;" : "=l"(d) : "l"(a), "l"(b));
    return d;
}
__device__ __forceinline__ u64 pack2(float lo, float hi) {
    u64 d; asm("mov.b64 %0, {%1, %2};" : "=l"(d) : "f"(lo), "f"(hi));
    return d;
}
__device__ __forceinline__ float unpack_sum(u64 v) {
    float lo, hi;
    asm("mov.b64 {%0, %1}, %2;" : "=f"(lo), "=f"(hi) : "l"(v));
    return lo + hi;
}
__device__ __forceinline__ float ex2a(float v) {
    float r; asm("ex2.approx.ftz.f32 %0, %1;" : "=f"(r) : "f"(v)); return r;
}
__device__ __forceinline__ float rcpa(float v) {
    float r; asm("rcp.approx.ftz.f32 %0, %1;" : "=f"(r) : "f"(v)); return r;
}

// Packed tanh of 2 values: t = (1-e)/(1+e), e = exp(-2v).
__device__ __forceinline__ u64 tanh2(u64 v2) {
    const u64 ONE2  = 0x3f8000003f800000ull;   // (1.0f, 1.0f)
    const u64 NEG12 = 0xbf800000bf800000ull;   // (-1.0f, -1.0f)
    const u64 SC2   = 0xc038aa3bc038aa3bull;   // (-2*log2e) x2
    u64 s2 = mul2(v2, SC2);
    float slo, shi;
    asm("mov.b64 {%0, %1}, %2;" : "=f"(slo), "=f"(shi) : "l"(s2));
    u64 e2 = pack2(ex2a(slo), ex2a(shi));
    u64 num = fma2(e2, NEG12, ONE2);           // 1 - e
    u64 den = add2(e2, ONE2);                  // 1 + e
    float dlo, dhi;
    asm("mov.b64 {%0, %1}, %2;" : "=f"(dlo), "=f"(dhi) : "l"(den));
    u64 r2 = pack2(rcpa(dlo), rcpa(dhi));
    return mul2(num, r2);
}

// ---------------- Prep: w[f] = sum_n hw[n]*coeffs[n,f] ----------------
__global__ void k_wprep(const float4* __restrict__ c4,
                        const float* __restrict__ hw, int N) {
    __shared__ float4 red[128];
    const int col = blockIdx.x;
    const int t   = threadIdx.x;
    float4 s = make_float4(0.f, 0.f, 0.f, 0.f);
    for (int n = t; n < N; n += 128) {
        float  h = hw[n];
        float4 v = c4[(size_t)n * F4DIM + col];
        s.x = fmaf(h, v.x, s.x);
        s.y = fmaf(h, v.y, s.y);
        s.z = fmaf(h, v.z, s.z);
        s.w = fmaf(h, v.w, s.w);
    }
    red[t] = s;
    __syncthreads();
    #pragma unroll
    for (int o = 64; o >= 1; o >>= 1) {
        if (t < o) {
            float4 b = red[t + o];
            red[t].x += b.x; red[t].y += b.y; red[t].z += b.z; red[t].w += b.w;
        }
        __syncthreads();
    }
    if (t == 0) ((float4*)g_w)[col] = red[0];
}

// Chebyshev -> monomial for one dim's 9 weights.
__device__ __forceinline__ void cheb2mono(const float* __restrict__ w, float* a) {
    a[0] = w[0] - w[2] + w[4] - w[6] + w[8];
    a[1] = w[1] - 3.f * w[3] + 5.f * w[5] - 7.f * w[7];
    a[2] = 2.f * w[2] - 8.f * w[4] + 18.f * w[6] - 32.f * w[8];
    a[3] = 4.f * w[3] - 20.f * w[5] + 56.f * w[7];
    a[4] = 8.f * w[4] - 48.f * w[6] + 160.f * w[8];
    a[5] = 16.f * w[5] - 112.f * w[7];
    a[6] = 32.f * w[6] - 256.f * w[8];
    a[7] = 64.f * w[7];
    a[8] = 128.f * w[8];
}

// ---------------- Main ----------------
// 256 threads = 8 warps, 32 rows/block, grid 1024 (8192 warps).
// Warp w: quarter q = w&3 (dims 64q..64q+63), row group g = w>>2
// (rows 16g..16g+15). Lane owns 2 fixed dims: d0 = 64q + 2*lane.
// Iter i: row 16g+i; lane reads x[row][d0..d0+1] (warp: 256B contiguous)
// through a 4-deep rolling prefetch buffer (4 outstanding LDG.64/warp),
// evaluates its packed Horner chain, STS partial. No shuffles/loop barriers.
__global__ void __launch_bounds__(256)
k_main(const float* __restrict__ x, float* __restrict__ out, int B) {
    __shared__ float part[ROWS][PPITCH];          // 16.5 KB
    __shared__ float red2[ROWS][9];               // 1.2 KB
    const int t    = threadIdx.x;
    const int lane = t & 31;
    const int w    = t >> 5;
    const int q    = w & 3;
    const int g    = w >> 2;
    const size_t row0 = (size_t)blockIdx.x * ROWS;

    // Coefficients for this lane's 2 dims, packed as one chain.
    u64 c[NF];
    {
        const int d0 = 64 * q + 2 * lane;
        const float2* wp = (const float2*)(g_w + d0 * NF);  // 18 floats, 8B-aligned
        float wb[2 * NF];
        #pragma unroll
        for (int k = 0; k < NF; ++k) ((float2*)wb)[k] = wp[k];
        float alo[NF], ahi[NF];
        cheb2mono(wb, alo);
        cheb2mono(wb + NF, ahi);
        #pragma unroll
        for (int j = 0; j < NF; ++j) c[j] = pack2(alo[j], ahi[j]);
    }

    // float2 index for row r: (row0 + 16g + r)*128 + 32q + lane.
    const float2* xp = (const float2*)x + (row0 + 16 * g) * 128 + 32 * q + lane;

    // 4-deep rolling prefetch: 4 outstanding LDG.64 per warp at all times.
    float2 buf[PF];
    #pragma unroll
    for (int k = 0; k < PF; ++k) buf[k] = xp[(size_t)k * 128];

    #pragma unroll
    for (int i = 0; i < 16; ++i) {
        float2 xv = buf[i % PF];
        if (i + PF < 16) buf[i % PF] = xp[(size_t)(i + PF) * 128];

        u64 tp = tanh2(pack2(xv.x, xv.y));
        u64 h  = c[DEG];
        #pragma unroll
        for (int j = DEG - 1; j >= 0; --j)
            h = fma2(tp, h, c[j]);
        part[16 * g + i][32 * q + lane] = unpack_sum(h);  // unique slot per warp
    }

    __syncthreads();
    // Tail reduce, step 1: 256 threads, each sums 16 of a row's 128 partials.
    {
        const int r = t >> 3, seg = t & 7;
        const float* pr = part[r] + 16 * seg;
        float s0 = 0.f, s1 = 0.f;
        #pragma unroll
        for (int k = 0; k < 16; k += 2) { s0 += pr[k]; s1 += pr[k + 1]; }
        red2[r][seg] = s0 + s1;
    }
    __syncthreads();
    // Step 2: 32 threads, each sums its row's 8 sub-partials.
    if (t < ROWS) {
        const float* rr = red2[t];
        float s = ((rr[0] + rr[1]) + (rr[2] + rr[3]))
                + ((rr[4] + rr[5]) + (rr[6] + rr[7]));
        size_t row = row0 + t;
        if (row < (size_t)B) out[row] = s;
    }
}

extern "C" void kernel_launch(void* const* d_in, const int* in_sizes, int n_in,
                              void* d_out, int out_size) {
    const float* x      = (const float*)d_in[0];
    const float* coeffs = (const float*)d_in[1];
    const float* hw     = (const float*)d_in[2];
    float* out = (float*)d_out;

    const int B = out_size;       // 32768 = 1024 * 32
    const int N = in_sizes[2];    // 256

    k_wprep<<<F4DIM, 128>>>((const float4*)coeffs, hw, N);
    k_main<<<(B + ROWS - 1) / ROWS, 256>>>(x, out, B);
}